// round 11
// baseline (speedup 1.0000x reference)
#include <cuda_runtime.h>
#include <stdint.h>

// ---------------- problem constants ----------------
#define C_IN   8
#define HW     256
#define M_OUT  8
#define P_OUT  254
#define PLANE  (P_OUT * P_OUT)

// ---------------- tiling ----------------
#define YB        6                         // output rows per block
#define ROWS_ST   (YB + 2)                  // 8 staged input rows
#define CH_STRIDE 264                       // mod 32 == 8 -> conflict-free LDS
#define ROW_STRIDE (C_IN * CH_STRIDE)       // 2112 words per staged row
#define SMEM_WORDS (ROWS_ST * ROW_STRIDE)   // 16896
#define SMEM_BYTES (SMEM_WORDS * 4)         // 67584 -> 3 CTAs/SM

__device__ __forceinline__ uint32_t f2tf32(float f) {
    uint32_t r;
    asm("cvt.rna.tf32.f32 %0, %1;" : "=r"(r) : "f"(f));
    return r;
}

__device__ __forceinline__ void load_row(uint32_t* A, const uint32_t* p, int tig) {
    // 12 values: [ch2*6 + {0,1,2}=px+0..2, {3,4,5}=px+8..10]; ch = tig + ch2*4
    #pragma unroll
    for (int ch2 = 0; ch2 < 2; ch2++) {
        const uint32_t* q = p + (tig + ch2 * 4) * CH_STRIDE;
        A[ch2 * 6 + 0] = q[0];
        A[ch2 * 6 + 1] = q[1];
        A[ch2 * 6 + 2] = q[2];
        A[ch2 * 6 + 3] = q[8];
        A[ch2 * 6 + 4] = q[9];
        A[ch2 * 6 + 5] = q[10];
    }
}

__global__ __launch_bounds__(256, 3)
void conv_mma_kernel(const float* __restrict__ in,
                     const float* __restrict__ flt,
                     float* __restrict__ out) {
    extern __shared__ uint32_t sin_[];   // tf32 bits: [row 0..7][c 0..7][px s264]

    const int tid  = threadIdx.x;
    const int w    = tid >> 5;
    const int lane = tid & 31;
    const int gid  = lane >> 2;       // 0..7 pixel group
    const int tig  = lane & 3;        // 0..3 channel group
    const int n    = blockIdx.y;
    const int y0   = blockIdx.x * YB;

    const float* inb = in + (size_t)n * (C_IN * HW * HW);

    // ---- stage input rows y0..y0+7 as TF32 bits (zero-fill OOB) ----
    #pragma unroll
    for (int it = 0; it < 16; it++) {
        int i   = tid + it * 256;     // 0..4095
        int row = i >> 9;             // 0..7
        int c   = (i >> 6) & 7;
        int x4  = i & 63;
        int gy  = y0 + row;
        float4 v = make_float4(0.f, 0.f, 0.f, 0.f);
        if (gy < HW) v = *(const float4*)(inb + (c * HW + gy) * HW + x4 * 4);
        uint4 t = make_uint4(f2tf32(v.x), f2tf32(v.y), f2tf32(v.z), f2tf32(v.w));
        *(uint4*)(sin_ + row * ROW_STRIDE + c * CH_STRIDE + x4 * 4) = t;
    }
    // zero pad columns 256..263 (loads touch px 256..257)
    for (int i = tid; i < ROWS_ST * C_IN * 8; i += 256) {
        int row = i >> 6;
        int c   = (i >> 3) & 7;
        sin_[row * ROW_STRIDE + c * CH_STRIDE + 256 + (i & 7)] = 0u;
    }

    // ---- B fragments: b0 = W[m=gid][c=tig][r][s], b1 = W[gid][tig+4][r][s] ----
    uint32_t b0[9], b1[9];
    #pragma unroll
    for (int rs = 0; rs < 9; rs++) {
        int r = rs / 3, s = rs % 3;
        b0[rs] = f2tf32(flt[((gid * 8 + tig) * 3 + r) * 3 + s]);
        b1[rs] = f2tf32(flt[((gid * 8 + tig + 4) * 3 + r) * 3 + s]);
    }
    __syncthreads();

    // ---- each warp: 2 x-columns of 16 px, sweep 6 y-rows with ring-3 A ----
    #pragma unroll 1
    for (int col = 0; col < 2; col++) {
        const int xb = (w + col * 8) * 16;
        const int g  = xb + gid;            // output px (group 0), <= 247
        const uint32_t* base = sin_ + g;

        uint32_t A[3][12];
        load_row(A[0], base + 0 * ROW_STRIDE, tig);
        load_row(A[1], base + 1 * ROW_STRIDE, tig);

        #pragma unroll
        for (int yi = 0; yi < YB; yi++) {
            load_row(A[(yi + 2) % 3], base + (yi + 2) * ROW_STRIDE, tig);

            // 3 independent accumulator chains, one per r
            float acc[3][4];
            #pragma unroll
            for (int r = 0; r < 3; r++)
                acc[r][0] = acc[r][1] = acc[r][2] = acc[r][3] = 0.f;

            #pragma unroll
            for (int s = 0; s < 3; s++) {
                #pragma unroll
                for (int r = 0; r < 3; r++) {     // consecutive MMAs -> different acc
                    const uint32_t* Ar = A[(yi + r) % 3];
                    const int rs = r * 3 + s;
                    asm volatile(
                        "mma.sync.aligned.m16n8k8.row.col.f32.tf32.tf32.f32 "
                        "{%0,%1,%2,%3}, {%4,%5,%6,%7}, {%8,%9}, {%0,%1,%2,%3};"
                        : "+f"(acc[r][0]), "+f"(acc[r][1]), "+f"(acc[r][2]), "+f"(acc[r][3])
                        : "r"(Ar[s]), "r"(Ar[3 + s]), "r"(Ar[6 + s]), "r"(Ar[9 + s]),
                          "r"(b0[rs]), "r"(b1[rs]));
                }
            }

            const int y = y0 + yi;
            if (y < P_OUT) {
                float c0 = acc[0][0] + acc[1][0] + acc[2][0];
                float c1 = acc[0][1] + acc[1][1] + acc[2][1];
                float c2 = acc[0][2] + acc[1][2] + acc[2][2];
                float c3 = acc[0][3] + acc[1][3] + acc[2][3];
                // C layout: c0:(px=g, m=2tig) c1:(g, 2tig+1) c2:(g+8, 2tig) c3:(g+8, 2tig+1)
                float* ob = out + (size_t)(n * M_OUT) * PLANE + (size_t)y * P_OUT;
                ob[(2 * tig    ) * PLANE + g] = c0;
                ob[(2 * tig + 1) * PLANE + g] = c1;
                if (g + 8 < P_OUT) {
                    ob[(2 * tig    ) * PLANE + g + 8] = c2;
                    ob[(2 * tig + 1) * PLANE + g + 8] = c3;
                }
            }
        }
    }
}

extern "C" void kernel_launch(void* const* d_in, const int* in_sizes, int n_in,
                              void* d_out, int out_size) {
    const float* in  = (const float*)d_in[0];   // (64, 8, 256, 256) fp32
    const float* flt = (const float*)d_in[1];   // (8, 8, 3, 3) fp32 OIHW
    float* out = (float*)d_out;                 // (64, 8, 254, 254) fp32

    (void)in_sizes; (void)n_in; (void)out_size;

    cudaFuncSetAttribute(conv_mma_kernel,
                         cudaFuncAttributeMaxDynamicSharedMemorySize, SMEM_BYTES);

    dim3 grid((P_OUT + YB - 1) / YB, 64);   // 43 y-blocks x 64 n
    conv_mma_kernel<<<grid, 256, SMEM_BYTES>>>(in, flt, out);
}

// round 12
// speedup vs baseline: 1.0339x; 1.0339x over previous
#include <cuda_runtime.h>
#include <stdint.h>

// ---------------- problem constants ----------------
#define C_IN   8
#define HW     256
#define M_OUT  8
#define P_OUT  254
#define PLANE  (P_OUT * P_OUT)

// ---------------- tiling ----------------
#define YB        8                         // output rows per block
#define ROWS_ST   (YB + 2)                  // 10 staged input rows
#define CH_STRIDE 264                       // mod 32 == 8 -> conflict-free LDS
#define ROW_STRIDE (C_IN * CH_STRIDE)       // 2112 words per staged row
#define SMEM_WORDS (ROWS_ST * ROW_STRIDE)   // 21120
#define SMEM_BYTES (SMEM_WORDS * 4)         // 84480
#define NJOBS     19                        // 18 tiles of 14 out-px + overlap tile

__device__ __forceinline__ uint32_t f2tf32(float f) {
    uint32_t r;
    asm("cvt.rna.tf32.f32 %0, %1;" : "=r"(r) : "f"(f));
    return r;
}

// Unshifted A fragment for one input row: a0=px g ch tig, a1=px g+8 ch tig,
// a2=px g ch tig+4, a3=px g+8 ch tig+4   (4 LDS.32, conflict-free)
__device__ __forceinline__ void load_frag(uint32_t* A, const uint32_t* q, int tig) {
    A[0] = q[tig * CH_STRIDE];
    A[1] = q[tig * CH_STRIDE + 8];
    A[2] = q[(tig + 4) * CH_STRIDE];
    A[3] = q[(tig + 4) * CH_STRIDE + 8];
}

__global__ __launch_bounds__(256, 2)
void conv_mma_kernel(const float* __restrict__ in,
                     const float* __restrict__ flt,
                     float* __restrict__ out) {
    extern __shared__ uint32_t sin_[];   // tf32 bits: [row 0..9][c 0..7][px s264]

    const int tid  = threadIdx.x;
    const int w    = tid >> 5;
    const int lane = tid & 31;
    const int gid  = lane >> 2;       // 0..7 pixel group
    const int tig  = lane & 3;        // 0..3 channel group
    const int n    = blockIdx.y;
    const int y0   = blockIdx.x * YB;

    const float* inb = in + (size_t)n * (C_IN * HW * HW);

    // ---- stage input rows y0..y0+9 as TF32 bits (zero-fill below image) ----
    #pragma unroll
    for (int it = 0; it < 20; it++) {
        int i   = tid + it * 256;     // 0..5119
        int row = i >> 9;             // 0..9
        int c   = (i >> 6) & 7;
        int x4  = i & 63;
        int gy  = y0 + row;
        float4 v = make_float4(0.f, 0.f, 0.f, 0.f);
        if (gy < HW) v = *(const float4*)(inb + (c * HW + gy) * HW + x4 * 4);
        uint4 t = make_uint4(f2tf32(v.x), f2tf32(v.y), f2tf32(v.z), f2tf32(v.w));
        *(uint4*)(sin_ + row * ROW_STRIDE + c * CH_STRIDE + x4 * 4) = t;
    }

    // ---- B fragments: b0[rs] = W[m=gid][c=tig][r][s], b1 = W[gid][tig+4][r][s] ----
    uint32_t b0[9], b1[9];
    #pragma unroll
    for (int rs = 0; rs < 9; rs++) {
        int r = rs / 3, s = rs % 3;
        b0[rs] = f2tf32(flt[((gid * 8 + tig) * 3 + r) * 3 + s]);
        b1[rs] = f2tf32(flt[((gid * 8 + tig + 4) * 3 + r) * 3 + s]);
    }
    __syncthreads();

    const unsigned l4 = (lane + 4) & 31;
    const unsigned l8 = (lane + 8) & 31;

    // ---- jobs: tile j covers out px [xb, xb+13]; fragment px [xb, xb+15] ----
    #pragma unroll 1
    for (int jt = 0; jt < 3; jt++) {
        const int j = w + jt * 8;
        if (j >= NJOBS) break;              // warp-uniform
        const int xb = (j < 18) ? j * 14 : 240;
        const int g  = xb + gid;            // fragment px group0 (max 247)
        const uint32_t* base = sin_ + g;

        uint32_t A[3][4];
        load_frag(A[0], base + 0 * ROW_STRIDE, tig);
        load_frag(A[1], base + 1 * ROW_STRIDE, tig);

        #pragma unroll
        for (int yi = 0; yi < YB; yi++) {
            load_frag(A[(yi + 2) % 3], base + (yi + 2) * ROW_STRIDE, tig);

            // acc[s] = D_s fragment: c0:(px g, m 2tig) c1:(g, 2tig+1)
            //                        c2:(g+8, 2tig)    c3:(g+8, 2tig+1)
            float acc[3][4];
            #pragma unroll
            for (int s = 0; s < 3; s++)
                acc[s][0] = acc[s][1] = acc[s][2] = acc[s][3] = 0.f;

            #pragma unroll
            for (int r = 0; r < 3; r++) {
                const uint32_t* Ar = A[(yi + r) % 3];
                #pragma unroll
                for (int s = 0; s < 3; s++) {   // consecutive MMAs -> different acc
                    const int rs = r * 3 + s;
                    asm volatile(
                        "mma.sync.aligned.m16n8k8.row.col.f32.tf32.tf32.f32 "
                        "{%0,%1,%2,%3}, {%4,%5,%6,%7}, {%8,%9}, {%0,%1,%2,%3};"
                        : "+f"(acc[s][0]), "+f"(acc[s][1]), "+f"(acc[s][2]), "+f"(acc[s][3])
                        : "r"(Ar[0]), "r"(Ar[1]), "r"(Ar[2]), "r"(Ar[3]),
                          "r"(b0[rs]), "r"(b1[rs]));
                }
            }

            const int y = y0 + yi;
            if (y < P_OUT) {                  // warp-uniform
                // shift-in-epilogue: out[px] = D0[px] + D1[px+1] + D2[px+2]
                float sh10 = __shfl_sync(0xffffffffu, acc[1][0], l4);
                float sh11 = __shfl_sync(0xffffffffu, acc[1][1], l4);
                float sh12 = __shfl_sync(0xffffffffu, acc[1][2], l4);
                float sh13 = __shfl_sync(0xffffffffu, acc[1][3], l4);
                float sh20 = __shfl_sync(0xffffffffu, acc[2][0], l8);
                float sh21 = __shfl_sync(0xffffffffu, acc[2][1], l8);
                float sh22 = __shfl_sync(0xffffffffu, acc[2][2], l8);
                float sh23 = __shfl_sync(0xffffffffu, acc[2][3], l8);

                // group0: out px g (gid 0..7 -> xb..xb+7)
                float d1g0 = (gid < 7) ? sh10 : sh12;   // D1[g+1]
                float d1g1 = (gid < 7) ? sh11 : sh13;
                float d2g0 = (gid < 6) ? sh20 : sh22;   // D2[g+2]
                float d2g1 = (gid < 6) ? sh21 : sh23;
                float o00 = acc[0][0] + d1g0 + d2g0;    // (g, 2tig)
                float o01 = acc[0][1] + d1g1 + d2g1;    // (g, 2tig+1)
                // group1: out px g+8 (gid 0..5 -> xb+8..xb+13)
                float o10 = acc[0][2] + sh12 + sh22;    // D1[g+9], D2[g+10]
                float o11 = acc[0][3] + sh13 + sh23;

                float* ob = out + (size_t)(n * M_OUT) * PLANE + (size_t)y * P_OUT;
                ob[(2 * tig    ) * PLANE + g] = o00;
                ob[(2 * tig + 1) * PLANE + g] = o01;
                if (gid < 6) {
                    ob[(2 * tig    ) * PLANE + g + 8] = o10;
                    ob[(2 * tig + 1) * PLANE + g + 8] = o11;
                }
            }
        }
    }
}

extern "C" void kernel_launch(void* const* d_in, const int* in_sizes, int n_in,
                              void* d_out, int out_size) {
    const float* in  = (const float*)d_in[0];   // (64, 8, 256, 256) fp32
    const float* flt = (const float*)d_in[1];   // (8, 8, 3, 3) fp32 OIHW
    float* out = (float*)d_out;                 // (64, 8, 254, 254) fp32

    (void)in_sizes; (void)n_in; (void)out_size;

    cudaFuncSetAttribute(conv_mma_kernel,
                         cudaFuncAttributeMaxDynamicSharedMemorySize, SMEM_BYTES);

    dim3 grid((P_OUT + YB - 1) / YB, 64);   // 32 y-blocks x 64 n
    conv_mma_kernel<<<grid, 256, SMEM_BYTES>>>(in, flt, out);
}